// round 7
// baseline (speedup 1.0000x reference)
#include <cuda_runtime.h>
#include <cuda_bf16.h>
#include <math.h>
#include <stdint.h>

#define FEAT 256
#define KTOT 2304
#define NCH 72                       // 32-k chunks per conv
#define TILEB 10240                  // A: 128 rows * 80 B (one hi or lo tile)
#define CHUNKB 20480                 // A hi+lo pair
#define BTILE 5120                   // B: 64 rows * 80 B
#define STAGEB 30720                 // A(20480) + Bh(5120) + Bl(5120)
#define CBLKB 1474560ULL             // 72 chunks (one 128-co block of a conv)
#define CONVPK 2949120ULL            // 2 co-blocks
#define HOFFP  35389440ULL           // after 12 tower convs
#define YSTRIDE 10485760ULL          // 256*40960 per tower
#define SMEM_TOTAL 61440             // 2 stages

__device__ float    g_bufA[3 * YSTRIDE];        // raw conv outputs (fp32, for GN)
__device__ uint32_t g_bufC[3 * YSTRIDE];        // packed (lo16|hi16) activations
__device__ float    g_bufP[16000000];
__device__ __align__(16) char g_wpk[39813120];
__device__ float    g_aff[3 * 512];
__device__ double   g_gpart[3 * 32 * 8 * 2];
__device__ float    g_biasA[81];

__device__ __forceinline__ uint32_t smem_u32(const void* p) {
    uint32_t a;
    asm("{ .reg .u64 t; cvta.to.shared.u64 t, %1; cvt.u32.u64 %0, t; }" : "=r"(a) : "l"(p));
    return a;
}
__device__ __forceinline__ void ldmx4(uint32_t* r, uint32_t addr) {
    asm volatile("ldmatrix.sync.aligned.m8n8.x4.shared.b16 {%0,%1,%2,%3},[%4];"
        : "=r"(r[0]), "=r"(r[1]), "=r"(r[2]), "=r"(r[3]) : "r"(addr));
}
__device__ __forceinline__ void mma_bf16(float* c, const uint32_t* a, const uint32_t* b) {
    asm volatile("mma.sync.aligned.m16n8k16.row.col.f32.bf16.bf16.f32 "
        "{%0,%1,%2,%3},{%4,%5,%6,%7},{%8,%9},{%0,%1,%2,%3};"
        : "+f"(c[0]), "+f"(c[1]), "+f"(c[2]), "+f"(c[3])
        : "r"(a[0]), "r"(a[1]), "r"(a[2]), "r"(a[3]), "r"(b[0]), "r"(b[1]));
}
__device__ __forceinline__ void cpa16(uint32_t dst, const void* src) {
    asm volatile("cp.async.cg.shared.global [%0], [%1], 16;" :: "r"(dst), "l"(src));
}
#define CP_COMMIT() asm volatile("cp.async.commit_group;" ::: "memory")
#define CP_WAIT0()  asm volatile("cp.async.wait_group 0;" ::: "memory")

__device__ __forceinline__ uint32_t packw(float v) {
    __nv_bfloat16 h = __float2bfloat16(v);
    __nv_bfloat16 l = __float2bfloat16(v - __bfloat162float(h));
    return (uint32_t)__bfloat16_as_ushort(h) | ((uint32_t)__bfloat16_as_ushort(l) << 16);
}

// ---- weight pack: w[co][ci][3][3] fp32 -> exact SMEM image (hi/lo bf16, padded)
__global__ void pack_tower(const float* __restrict__ w0, const float* __restrict__ w1,
                           const float* __restrict__ w2, char* __restrict__ dst) {
    long long idx = (long long)blockIdx.x * blockDim.x + threadIdx.x;
    if (idx >= 12LL * 256 * KTOT) return;
    int k = (int)(idx % KTOT);
    int coall = (int)(idx / KTOT);
    int conv = coall >> 8, co = coall & 255;
    int t = conv >> 2, i = conv & 3;
    const float* w = (t == 0 ? w0 : (t == 1 ? w1 : w2)) + (size_t)i * 256 * KTOT;
    int rs = k >> 8, ci = k & 255;
    float val = w[(size_t)co * KTOT + ci * 9 + rs];
    __nv_bfloat16 hi = __float2bfloat16(val);
    __nv_bfloat16 lo = __float2bfloat16(val - __bfloat162float(hi));
    int c = k >> 5, kk = k & 31, cbk = co >> 7, row = co & 127;
    char* tb = dst + (size_t)conv * CONVPK + (size_t)cbk * CBLKB + (size_t)c * CHUNKB;
    *(__nv_bfloat16*)(tb + row * 80 + kk * 2) = hi;
    *(__nv_bfloat16*)(tb + TILEB + row * 80 + kk * 2) = lo;
}

__global__ void pack_head(const float* __restrict__ w1, const float* __restrict__ w2,
                          int C1, int C2, char* __restrict__ dst) {
    int idx = blockIdx.x * blockDim.x + threadIdx.x;
    if (idx >= 128 * KTOT) return;
    int k = idx % KTOT, row = idx / KTOT;
    int rs = k >> 8, ci = k & 255;
    float val = 0.f;
    if (row < C1) val = w1[(size_t)row * KTOT + ci * 9 + rs];
    else if (row < C1 + C2) val = w2[(size_t)(row - C1) * KTOT + ci * 9 + rs];
    __nv_bfloat16 hi = __float2bfloat16(val);
    __nv_bfloat16 lo = __float2bfloat16(val - __bfloat162float(hi));
    int c = k >> 5, kk = k & 31;
    char* tb = dst + (size_t)c * CHUNKB;
    *(__nv_bfloat16*)(tb + row * 80 + kk * 2) = hi;
    *(__nv_bfloat16*)(tb + TILEB + row * 80 + kk * 2) = lo;
}

__global__ void build_biasA(const float* __restrict__ bc, const float* __restrict__ bt,
                            float* __restrict__ out) {
    int i = threadIdx.x;
    if (i < 80) out[i] = bc[i];
    else if (i == 80) out[80] = bt[0];
}

// ---- activation pre-convert: fp32 (+optional GN affine/ReLU) -> packed lo|hi u32
__global__ void cvt_act(const float* __restrict__ y, const float* __restrict__ aff,
                        uint32_t* __restrict__ o, int HW, int nT) {
    int HW4 = HW >> 2;
    int CHW4 = 256 * HW4;
    int idx = blockIdx.x * blockDim.x + threadIdx.x;
    if (idx >= nT * CHW4) return;
    int t = idx / CHW4, r = idx - t * CHW4;
    int c = r / HW4, p = (r - c * HW4) << 2;
    size_t off = (size_t)t * YSTRIDE + (size_t)c * HW + p;
    float4 v = *(const float4*)(y + off);
    if (aff) {
        float a = aff[t * 512 + c], b = aff[t * 512 + 256 + c];
        v.x = fmaxf(fmaf(v.x, a, b), 0.f);
        v.y = fmaxf(fmaf(v.y, a, b), 0.f);
        v.z = fmaxf(fmaf(v.z, a, b), 0.f);
        v.w = fmaxf(fmaf(v.w, a, b), 0.f);
    }
    uint4 w;
    w.x = packw(v.x); w.y = packw(v.y); w.z = packw(v.z); w.w = packw(v.w);
    *(uint4*)(o + off) = w;
}

// ---- GroupNorm stats: two-stage, fp64, deterministic -----------------------
__global__ void gn_part(const float* __restrict__ y, int HW, int Sg,
                        double* __restrict__ part) {
    __shared__ double sh[256], sh2[256];
    int b = blockIdx.x;
    int s = b % Sg; int tg = b / Sg; int g = tg & 31; int t = tg >> 5;
    const float* base = y + (size_t)t * YSTRIDE + (size_t)g * 8 * HW;
    int n = 8 * HW, cn = n / Sg, st = s * cn;
    double acc = 0.0, acc2 = 0.0;
    for (int i = st + threadIdx.x; i < st + cn; i += 256) {
        double v = (double)base[i]; acc += v; acc2 += v * v;
    }
    int tid = threadIdx.x;
    sh[tid] = acc; sh2[tid] = acc2;
    __syncthreads();
    for (int o = 128; o > 0; o >>= 1) {
        if (tid < o) { sh[tid] += sh[tid + o]; sh2[tid] += sh2[tid + o]; }
        __syncthreads();
    }
    if (tid == 0) { part[b * 2] = sh[0]; part[b * 2 + 1] = sh2[0]; }
}

__global__ void gn_fin(const double* __restrict__ part, int Sg, int HW,
                       const float* __restrict__ g0, const float* __restrict__ g1,
                       const float* __restrict__ g2,
                       const float* __restrict__ b0, const float* __restrict__ b1,
                       const float* __restrict__ b2, float* __restrict__ aff) {
    int tid = threadIdx.x;                 // 768
    int t = tid >> 8, c = tid & 255, g = c >> 3;
    const float* gp = (t == 0) ? g0 : ((t == 1) ? g1 : g2);
    const float* bp = (t == 0) ? b0 : ((t == 1) ? b1 : b2);
    int pb = (t * 32 + g) * Sg;
    double s = 0.0, s2 = 0.0;
    for (int i = 0; i < Sg; i++) { s += part[(pb + i) * 2]; s2 += part[(pb + i) * 2 + 1]; }
    double n = 8.0 * HW;
    double mean = s / n, var = s2 / n - mean * mean;
    float a = (float)((double)gp[c] * rsqrt(var + 1e-5));
    aff[t * 512 + c] = a;
    aff[t * 512 + 256 + c] = bp[c] - (float)mean * a;
}

// ---- bf16 3-pass implicit-GEMM conv: 128co x 64px x 32k chunks -------------
// 2 CTAs/SM: small tile + <=128 regs so fill/barrier of one CTA hides under
// the other CTA's HMMA stream.
__global__ __launch_bounds__(256, 2)
void conv_mma(const uint32_t* __restrict__ x, const char* __restrict__ wpk,
              float* __restrict__ out, float* __restrict__ out2,
              int H, int W, int Cout, int nCB, int chunksPerZ,
              int mode, const float* __restrict__ bias,
              const float* __restrict__ scale_ptr, int split,
              size_t xT, size_t wT, size_t yT) {
    extern __shared__ char smem[];
    const int HW = H * W;
    int tid = threadIdx.x, lane = tid & 31, wid = tid >> 5;
    int yb = blockIdx.y;
    int tw = yb / nCB, cb = yb - tw * nCB;
    x   += (size_t)tw * xT;
    wpk += (size_t)tw * wT + (size_t)cb * CBLKB;
    out += (size_t)tw * yT;

    uint32_t sb = smem_u32(smem);
    int px0 = blockIdx.x * 64;
    int co0 = cb * 128;

    // B fill: 64 px x 32 k; thread -> pxl=tid&63, kseg=tid>>6 (8 k each)
    int pxl = tid & 63, kseg = tid >> 6;
    int p = px0 + pxl;
    bool pv = p < HW;
    int h0 = 0, w0 = 0;
    if (pv) { h0 = p / W; w0 = p - h0 * W; }

    // warp tiling: 4(co) x 2(px): 32 co x 32 px per warp
    int co_w = (wid & 3) * 32;
    int px_w = (wid >> 2) * 32;

    int aoff[2], boff[2];
#pragma unroll
    for (int mi = 0; mi < 2; mi++)
        aoff[mi] = (co_w + mi * 16 + (lane & 15)) * 80 + ((lane >> 4) * 16);
#pragma unroll
    for (int np = 0; np < 2; np++) {
        int rowB = px_w + np * 16 + ((lane >> 4) << 3) + (lane & 7);
        boff[np] = rowB * 80 + (((lane >> 3) & 1) * 16);
    }

    float acc[2][4][4];
#pragma unroll
    for (int mi = 0; mi < 2; mi++)
#pragma unroll
        for (int ni = 0; ni < 4; ni++)
#pragma unroll
            for (int q = 0; q < 4; q++) acc[mi][ni][q] = 0.f;

    int c0 = blockIdx.z * chunksPerZ;
    uint32_t xw[8];

    auto cpaA = [&](int buf, int cg) {
        const char* src = wpk + (size_t)cg * CHUNKB + tid * 16;
        uint32_t dst = sb + buf * STAGEB + tid * 16;
#pragma unroll
        for (int i = 0; i < 5; i++)
            cpa16(dst + i * 4096, src + i * 4096);
    };
    auto loadB = [&](int cg) {
        int rs = cg >> 3, ci0 = (cg & 7) * 32;
        int r = rs / 3, s = rs - 3 * (rs / 3);
        int hh = h0 + r - 1, ww = w0 + s - 1;
        bool v = pv && (unsigned)hh < (unsigned)H && (unsigned)ww < (unsigned)W;
        const uint32_t* xp = x + (size_t)(ci0 + kseg * 8) * HW + (v ? (hh * W + ww) : 0);
#pragma unroll
        for (int j = 0; j < 8; j++) xw[j] = v ? xp[(size_t)j * HW] : 0u;
    };
    auto storeB = [&](int buf) {
        char* Bh = smem + buf * STAGEB + CHUNKB;
        char* Bl = Bh + BTILE;
        int off = pxl * 80 + kseg * 16;
#pragma unroll
        for (int j = 0; j < 8; j += 2) {
            *(uint32_t*)(Bh + off + j * 2) = __byte_perm(xw[j], xw[j + 1], 0x5410);
            *(uint32_t*)(Bl + off + j * 2) = __byte_perm(xw[j], xw[j + 1], 0x7632);
        }
    };
    auto compute = [&](int buf) {
        uint32_t Ab = sb + buf * STAGEB;
        uint32_t Bb = Ab + CHUNKB;
#pragma unroll
        for (int ks = 0; ks < 2; ks++) {
            uint32_t ahi[2][4], alo[2][4], bhi[4][2], blo[4][2];
#pragma unroll
            for (int mi = 0; mi < 2; mi++) {
                ldmx4(ahi[mi], Ab + aoff[mi] + ks * 32);
                ldmx4(alo[mi], Ab + TILEB + aoff[mi] + ks * 32);
            }
#pragma unroll
            for (int np = 0; np < 2; np++) {
                uint32_t r[4];
                ldmx4(r, Bb + boff[np] + ks * 32);
                bhi[2 * np][0] = r[0]; bhi[2 * np][1] = r[1];
                bhi[2 * np + 1][0] = r[2]; bhi[2 * np + 1][1] = r[3];
                ldmx4(r, Bb + BTILE + boff[np] + ks * 32);
                blo[2 * np][0] = r[0]; blo[2 * np][1] = r[1];
                blo[2 * np + 1][0] = r[2]; blo[2 * np + 1][1] = r[3];
            }
#pragma unroll
            for (int mi = 0; mi < 2; mi++)
#pragma unroll
                for (int ni = 0; ni < 4; ni++) {
                    mma_bf16(acc[mi][ni], ahi[mi], bhi[ni]);
                    mma_bf16(acc[mi][ni], ahi[mi], blo[ni]);
                    mma_bf16(acc[mi][ni], alo[mi], bhi[ni]);
                }
        }
    };

    // prologue
    cpaA(0, c0); CP_COMMIT();
    loadB(c0); storeB(0);
    CP_WAIT0();
    __syncthreads();

    int buf = 0;
    for (int it = 0; it < chunksPerZ; it++) {
        bool more = (it + 1) < chunksPerZ;
        if (more) { cpaA(buf ^ 1, c0 + it + 1); CP_COMMIT(); loadB(c0 + it + 1); }
        compute(buf);
        if (more) { storeB(buf ^ 1); CP_WAIT0(); }
        __syncthreads();
        buf ^= 1;
    }

    // epilogue
    float scl = (mode == 2) ? *scale_ptr : 1.f;
    size_t zoff = (size_t)blockIdx.z * (size_t)Cout * HW;
    int gid = lane >> 2, tig = lane & 3;
#pragma unroll
    for (int mi = 0; mi < 2; mi++) {
#pragma unroll
        for (int rh = 0; rh < 2; rh++) {
            int co = co0 + co_w + mi * 16 + gid + rh * 8;
            if (co >= Cout) continue;
            float bv = (mode != 0) ? bias[co] : 0.f;
            float* ob = out; int coo = co;
            if (mode == 1 && co >= split) { ob = out2; coo = co - split; }
            size_t base = (mode == 0 ? zoff : (size_t)0) + (size_t)coo * HW;
#pragma unroll
            for (int ni = 0; ni < 4; ni++) {
                int px = px0 + px_w + ni * 8 + tig * 2;
                if (px >= HW) continue;
                float v0 = acc[mi][ni][rh * 2], v1 = acc[mi][ni][rh * 2 + 1];
                if (mode == 1) { v0 += bv; v1 += bv; }
                else if (mode == 2) { v0 = expf((v0 + bv) * scl); v1 = expf((v1 + bv) * scl); }
                float2 vv = {v0, v1};
                *(float2*)(ob + base + px) = vv;
            }
        }
    }
}

// ---- split-K reduces --------------------------------------------------------
__global__ void reduce_t(const float* __restrict__ part, int S, int HW,
                         float* __restrict__ out) {
    int idx = blockIdx.x * blockDim.x + threadIdx.x;
    int CHW = 256 * HW;
    if (idx >= 3 * CHW) return;
    int t = idx / CHW, r = idx - t * CHW;
    const float* p = part + (size_t)t * S * CHW + r;
    float s = 0.f;
    for (int j = 0; j < S; j++) s += p[(size_t)j * CHW];
    out[(size_t)t * YSTRIDE + r] = s;
}

__global__ void reduce_ep(const float* __restrict__ part, int S, int Cout, int HW,
                          float* __restrict__ out, float* __restrict__ out2,
                          int mode, const float* __restrict__ bias,
                          const float* __restrict__ scale_ptr, int split) {
    int i = blockIdx.x * blockDim.x + threadIdx.x;
    int CHW = Cout * HW;
    if (i >= CHW) return;
    float s = 0.f;
    for (int j = 0; j < S; j++) s += part[(size_t)j * CHW + i];
    int co = i / HW;
    float bv = (bias != nullptr) ? bias[co] : 0.f;
    if (mode == 2) { out[i] = expf((s + bv) * (*scale_ptr)); return; }
    int p = i - co * HW;
    if (co >= split) out2[(size_t)(co - split) * HW + p] = s + bv;
    else             out [(size_t)co * HW + p]           = s + bv;
}

// ---- host -------------------------------------------------------------------
extern "C" void kernel_launch(void* const* d_in, const int* in_sizes, int n_in,
                              void* d_out, int out_size) {
    (void)in_sizes; (void)n_in; (void)out_size;
    const float* feat[5];
    for (int l = 0; l < 5; l++) feat[l] = (const float*)d_in[l];
    const float* tw[3] = {(const float*)d_in[5], (const float*)d_in[8], (const float*)d_in[11]};
    const float* tg[3] = {(const float*)d_in[6], (const float*)d_in[9], (const float*)d_in[12]};
    const float* tb[3] = {(const float*)d_in[7], (const float*)d_in[10], (const float*)d_in[13]};
    const float* pcls_w = (const float*)d_in[14];
    const float* pcls_b = (const float*)d_in[15];
    const float* preg_w = (const float*)d_in[16];
    const float* preg_b = (const float*)d_in[17];
    const float* pmsk_w = (const float*)d_in[18];
    const float* pmsk_b = (const float*)d_in[19];
    const float* pctr_w = (const float*)d_in[20];
    const float* pctr_b = (const float*)d_in[21];
    const float* sc_bbox = (const float*)d_in[22];
    const float* sc_mask = (const float*)d_in[23];
    float* outf = (float*)d_out;

    float *bufA, *bufP, *aff, *biasA;
    uint32_t* bufC;
    double* gpart;
    char* wpk;
    cudaGetSymbolAddress((void**)&bufA, g_bufA);
    cudaGetSymbolAddress((void**)&bufC, g_bufC);
    cudaGetSymbolAddress((void**)&bufP, g_bufP);
    cudaGetSymbolAddress((void**)&wpk, g_wpk);
    cudaGetSymbolAddress((void**)&aff, g_aff);
    cudaGetSymbolAddress((void**)&gpart, g_gpart);
    cudaGetSymbolAddress((void**)&biasA, g_biasA);

    cudaFuncSetAttribute(conv_mma, cudaFuncAttributeMaxDynamicSharedMemorySize, SMEM_TOTAL);

    long long tot = 12LL * 256 * KTOT;
    pack_tower<<<(unsigned)((tot + 255) / 256), 256>>>(tw[0], tw[1], tw[2], wpk);
    pack_head<<<(128 * KTOT + 255) / 256, 256>>>(pcls_w, pctr_w, 80, 1, wpk + HOFFP);
    pack_head<<<(128 * KTOT + 255) / 256, 256>>>(preg_w, nullptr, 4, 0, wpk + HOFFP + CBLKB);
    pack_head<<<(128 * KTOT + 255) / 256, 256>>>(pmsk_w, nullptr, 36, 0, wpk + HOFFP + 2 * CBLKB);
    build_biasA<<<1, 128>>>(pcls_b, pctr_b, biasA);

    static const int Hs[5]  = {160, 80, 40, 20, 10};
    static const int Wss[5] = {256, 128, 64, 32, 16};
    static const int Sl[5]  = {1, 1, 2, 6, 12};
    static const int Sgl[5] = {4, 2, 1, 1, 1};
    static const size_t PHW[5] = {0, 40960, 51200, 53760, 54400};
    const size_t TOT = 54560;
    const size_t clsBase = 0, bboxBase = 80 * TOT, ctrBase = 84 * TOT, maskBase = 85 * TOT;
    const int BIG = 1 << 30;

    for (int l = 0; l < 5; l++) {
        int H = Hs[l], W = Wss[l], HW = H * W;
        int S = Sl[l], cpz = NCH / S, Sg = Sgl[l];
        int gx = (HW + 63) / 64;
        cvt_act<<<(256 * (HW >> 2) + 255) / 256, 256>>>(feat[l], nullptr, bufC, HW, 1);
        size_t xT = 0;
        for (int i = 0; i < 4; i++) {
            const char* wc = wpk + (size_t)i * CONVPK;
            if (S == 1) {
                conv_mma<<<dim3(gx, 6, 1), 256, SMEM_TOTAL>>>(bufC, wc, bufA, nullptr,
                    H, W, 256, 2, cpz, 0, nullptr, nullptr, BIG, xT, 4 * CONVPK, YSTRIDE);
            } else {
                size_t PS = (size_t)S * 256 * HW;
                conv_mma<<<dim3(gx, 6, S), 256, SMEM_TOTAL>>>(bufC, wc, bufP, nullptr,
                    H, W, 256, 2, cpz, 0, nullptr, nullptr, BIG, xT, 4 * CONVPK, PS);
                reduce_t<<<(3 * 256 * HW + 255) / 256, 256>>>(bufP, S, HW, bufA);
            }
            gn_part<<<3 * 32 * Sg, 256>>>(bufA, HW, Sg, gpart);
            gn_fin<<<1, 768>>>(gpart, Sg, HW,
                tg[0] + i * FEAT, tg[1] + i * FEAT, tg[2] + i * FEAT,
                tb[0] + i * FEAT, tb[1] + i * FEAT, tb[2] + i * FEAT, aff);
            cvt_act<<<(3 * 256 * (HW >> 2) + 255) / 256, 256>>>(bufA, aff, bufC, HW, 3);
            xT = YSTRIDE;
        }
        for (int t = 0; t < 3; t++) {
            const uint32_t* hx = bufC + (size_t)t * YSTRIDE;
            const char* hw = wpk + HOFFP + (size_t)t * CBLKB;
            int Cout, mode, split = BIG;
            const float* bias; const float* scp = nullptr;
            float *o1, *o2 = nullptr;
            if (t == 0) {
                Cout = 81; mode = 1; split = 80; bias = biasA;
                o1 = outf + clsBase + 80 * PHW[l];
                o2 = outf + ctrBase + PHW[l];
            } else if (t == 1) {
                Cout = 4; mode = 2; bias = preg_b; scp = sc_bbox + l;
                o1 = outf + bboxBase + 4 * PHW[l];
            } else {
                Cout = 36; mode = 2; bias = pmsk_b; scp = sc_mask + l;
                o1 = outf + maskBase + 36 * PHW[l];
            }
            if (S == 1) {
                conv_mma<<<dim3(gx, 1, 1), 256, SMEM_TOTAL>>>(hx, hw, o1, o2,
                    H, W, Cout, 1, cpz, mode, bias, scp, split, 0, 0, 0);
            } else {
                conv_mma<<<dim3(gx, 1, S), 256, SMEM_TOTAL>>>(hx, hw, bufP, nullptr,
                    H, W, Cout, 1, cpz, 0, nullptr, nullptr, BIG, 0, 0, 0);
                reduce_ep<<<(Cout * HW + 255) / 256, 256>>>(bufP, S, Cout, HW,
                    o1, o2, mode, bias, scp, split);
            }
        }
    }
}

// round 8
// speedup vs baseline: 1.7316x; 1.7316x over previous
#include <cuda_runtime.h>
#include <cuda_fp16.h>
#include <math.h>
#include <stdint.h>

#define FEAT 256
#define KTOT 2304
#define NCH 72                       // 32-k chunks per conv
#define CHUNKB 10240                 // A: 128 rows * 80 B (fp16 weights, single tile)
#define BTILE 10240                  // B: 128 rows * 80 B (one of xh / xl)
#define STAGEB 30720                 // A + Bh + Bl
#define CBLKB 737280ULL              // 72 chunks (one 128-co block of a conv)
#define CONVPK 1474560ULL            // 2 co-blocks
#define HOFFP  17694720ULL           // after 12 tower convs
#define YSTRIDE 10485760ULL          // 256*40960 per tower
#define SMEM_TOTAL 61440             // 2 stages

__device__ float    g_bufA[3 * YSTRIDE];        // raw conv outputs (fp32, for GN)
__device__ uint32_t g_bufC[3 * YSTRIDE];        // packed (xl16|xh16) activations
__device__ float    g_bufP[16000000];
__device__ __align__(16) char g_wpk[19906560];
__device__ float    g_aff[3 * 512];
__device__ double   g_gpart[3 * 32 * 8 * 2];
__device__ float    g_biasA[81];

__device__ __forceinline__ uint32_t smem_u32(const void* p) {
    uint32_t a;
    asm("{ .reg .u64 t; cvta.to.shared.u64 t, %1; cvt.u32.u64 %0, t; }" : "=r"(a) : "l"(p));
    return a;
}
__device__ __forceinline__ void ldmx4(uint32_t* r, uint32_t addr) {
    asm volatile("ldmatrix.sync.aligned.m8n8.x4.shared.b16 {%0,%1,%2,%3},[%4];"
        : "=r"(r[0]), "=r"(r[1]), "=r"(r[2]), "=r"(r[3]) : "r"(addr));
}
__device__ __forceinline__ void mma_f16(float* c, const uint32_t* a, const uint32_t* b) {
    asm volatile("mma.sync.aligned.m16n8k16.row.col.f32.f16.f16.f32 "
        "{%0,%1,%2,%3},{%4,%5,%6,%7},{%8,%9},{%0,%1,%2,%3};"
        : "+f"(c[0]), "+f"(c[1]), "+f"(c[2]), "+f"(c[3])
        : "r"(a[0]), "r"(a[1]), "r"(a[2]), "r"(a[3]), "r"(b[0]), "r"(b[1]));
}
__device__ __forceinline__ void cpa16(uint32_t dst, const void* src) {
    asm volatile("cp.async.cg.shared.global [%0], [%1], 16;" :: "r"(dst), "l"(src));
}
#define CP_COMMIT() asm volatile("cp.async.commit_group;" ::: "memory")
#define CP_WAIT0()  asm volatile("cp.async.wait_group 0;" ::: "memory")

// exact fp16 split of an fp32 activation: low 16 bits = xh, high = residual xl
__device__ __forceinline__ uint32_t packa(float v) {
    __half h = __float2half_rn(v);
    __half l = __float2half_rn(v - __half2float(h));
    return (uint32_t)__half_as_ushort(h) | ((uint32_t)__half_as_ushort(l) << 16);
}

// ---- weight pack: w[co][ci][3][3] fp32 -> fp16 SMEM image (padded rows) ----
__global__ void pack_tower(const float* __restrict__ w0, const float* __restrict__ w1,
                           const float* __restrict__ w2, char* __restrict__ dst) {
    long long idx = (long long)blockIdx.x * blockDim.x + threadIdx.x;
    if (idx >= 12LL * 256 * KTOT) return;
    int k = (int)(idx % KTOT);
    int coall = (int)(idx / KTOT);
    int conv = coall >> 8, co = coall & 255;
    int t = conv >> 2, i = conv & 3;
    const float* w = (t == 0 ? w0 : (t == 1 ? w1 : w2)) + (size_t)i * 256 * KTOT;
    int rs = k >> 8, ci = k & 255;
    float val = w[(size_t)co * KTOT + ci * 9 + rs];
    int c = k >> 5, kk = k & 31, cbk = co >> 7, row = co & 127;
    char* tb = dst + (size_t)conv * CONVPK + (size_t)cbk * CBLKB + (size_t)c * CHUNKB;
    *(__half*)(tb + row * 80 + kk * 2) = __float2half_rn(val);
}

__global__ void pack_head(const float* __restrict__ w1, const float* __restrict__ w2,
                          int C1, int C2, char* __restrict__ dst) {
    int idx = blockIdx.x * blockDim.x + threadIdx.x;
    if (idx >= 128 * KTOT) return;
    int k = idx % KTOT, row = idx / KTOT;
    int rs = k >> 8, ci = k & 255;
    float val = 0.f;
    if (row < C1) val = w1[(size_t)row * KTOT + ci * 9 + rs];
    else if (row < C1 + C2) val = w2[(size_t)(row - C1) * KTOT + ci * 9 + rs];
    int c = k >> 5, kk = k & 31;
    char* tb = dst + (size_t)c * CHUNKB;
    *(__half*)(tb + row * 80 + kk * 2) = __float2half_rn(val);
}

__global__ void build_biasA(const float* __restrict__ bc, const float* __restrict__ bt,
                            float* __restrict__ out) {
    int i = threadIdx.x;
    if (i < 80) out[i] = bc[i];
    else if (i == 80) out[80] = bt[0];
}

// ---- activation pre-convert: fp32 (+optional GN affine/ReLU) -> packed xl|xh
__global__ void cvt_act(const float* __restrict__ y, const float* __restrict__ aff,
                        uint32_t* __restrict__ o, int HW, int nT) {
    int HW4 = HW >> 2;
    int CHW4 = 256 * HW4;
    int idx = blockIdx.x * blockDim.x + threadIdx.x;
    if (idx >= nT * CHW4) return;
    int t = idx / CHW4, r = idx - t * CHW4;
    int c = r / HW4, p = (r - c * HW4) << 2;
    size_t off = (size_t)t * YSTRIDE + (size_t)c * HW + p;
    float4 v = *(const float4*)(y + off);
    if (aff) {
        float a = aff[t * 512 + c], b = aff[t * 512 + 256 + c];
        v.x = fmaxf(fmaf(v.x, a, b), 0.f);
        v.y = fmaxf(fmaf(v.y, a, b), 0.f);
        v.z = fmaxf(fmaf(v.z, a, b), 0.f);
        v.w = fmaxf(fmaf(v.w, a, b), 0.f);
    }
    uint4 w;
    w.x = packa(v.x); w.y = packa(v.y); w.z = packa(v.z); w.w = packa(v.w);
    *(uint4*)(o + off) = w;
}

// ---- GroupNorm stats: two-stage, fp64, deterministic -----------------------
__global__ void gn_part(const float* __restrict__ y, int HW, int Sg,
                        double* __restrict__ part) {
    __shared__ double sh[256], sh2[256];
    int b = blockIdx.x;
    int s = b % Sg; int tg = b / Sg; int g = tg & 31; int t = tg >> 5;
    const float* base = y + (size_t)t * YSTRIDE + (size_t)g * 8 * HW;
    int n = 8 * HW, cn = n / Sg, st = s * cn;
    double acc = 0.0, acc2 = 0.0;
    for (int i = st + threadIdx.x; i < st + cn; i += 256) {
        double v = (double)base[i]; acc += v; acc2 += v * v;
    }
    int tid = threadIdx.x;
    sh[tid] = acc; sh2[tid] = acc2;
    __syncthreads();
    for (int o = 128; o > 0; o >>= 1) {
        if (tid < o) { sh[tid] += sh[tid + o]; sh2[tid] += sh2[tid + o]; }
        __syncthreads();
    }
    if (tid == 0) { part[b * 2] = sh[0]; part[b * 2 + 1] = sh2[0]; }
}

__global__ void gn_fin(const double* __restrict__ part, int Sg, int HW,
                       const float* __restrict__ g0, const float* __restrict__ g1,
                       const float* __restrict__ g2,
                       const float* __restrict__ b0, const float* __restrict__ b1,
                       const float* __restrict__ b2, float* __restrict__ aff) {
    int tid = threadIdx.x;                 // 768
    int t = tid >> 8, c = tid & 255, g = c >> 3;
    const float* gp = (t == 0) ? g0 : ((t == 1) ? g1 : g2);
    const float* bp = (t == 0) ? b0 : ((t == 1) ? b1 : b2);
    int pb = (t * 32 + g) * Sg;
    double s = 0.0, s2 = 0.0;
    for (int i = 0; i < Sg; i++) { s += part[(pb + i) * 2]; s2 += part[(pb + i) * 2 + 1]; }
    double n = 8.0 * HW;
    double mean = s / n, var = s2 / n - mean * mean;
    float a = (float)((double)gp[c] * rsqrt(var + 1e-5));
    aff[t * 512 + c] = a;
    aff[t * 512 + 256 + c] = bp[c] - (float)mean * a;
}

// ---- f16 2-pass implicit-GEMM conv: 128co x 128px x 32k chunks -------------
// y = (xh + xl) . wh  — activations exact (fp16 split), weights fp16-rounded.
__global__ __launch_bounds__(256, 1)
void conv_mma(const uint32_t* __restrict__ x, const char* __restrict__ wpk,
              float* __restrict__ out, float* __restrict__ out2,
              int H, int W, int Cout, int nCB, int chunksPerZ,
              int mode, const float* __restrict__ bias,
              const float* __restrict__ scale_ptr, int split,
              size_t xT, size_t wT, size_t yT) {
    extern __shared__ char smem[];
    const int HW = H * W;
    int tid = threadIdx.x, lane = tid & 31, wid = tid >> 5;
    int yb = blockIdx.y;
    int tw = yb / nCB, cb = yb - tw * nCB;
    x   += (size_t)tw * xT;
    wpk += (size_t)tw * wT + (size_t)cb * CBLKB;
    out += (size_t)tw * yT;

    uint32_t sb = smem_u32(smem);
    int px0 = blockIdx.x * 128;
    int co0 = cb * 128;

    int pxl = tid & 127, kh = tid >> 7;
    int p = px0 + pxl;
    bool pv = p < HW;
    int h0 = 0, w0 = 0;
    if (pv) { h0 = p / W; w0 = p - h0 * W; }

    int co_w = (wid & 3) * 32;
    int px_w = (wid >> 2) * 64;

    int aoff[2], boff[4];
#pragma unroll
    for (int mi = 0; mi < 2; mi++)
        aoff[mi] = (co_w + mi * 16 + (lane & 15)) * 80 + ((lane >> 4) * 16);
#pragma unroll
    for (int np = 0; np < 4; np++) {
        int rowB = px_w + np * 16 + ((lane >> 4) << 3) + (lane & 7);
        boff[np] = rowB * 80 + (((lane >> 3) & 1) * 16);
    }

    float acc[2][8][4];
#pragma unroll
    for (int mi = 0; mi < 2; mi++)
#pragma unroll
        for (int ni = 0; ni < 8; ni++)
#pragma unroll
            for (int q = 0; q < 4; q++) acc[mi][ni][q] = 0.f;

    int c0 = blockIdx.z * chunksPerZ;
    uint32_t xw[16];

    auto cpaA = [&](int buf, int cg) {
        const char* src = wpk + (size_t)cg * CHUNKB;
        uint32_t dst = sb + buf * STAGEB;
#pragma unroll
        for (int i = 0; i < 3; i++) {
            int idx = tid + i * 256;
            if (idx < 640) cpa16(dst + idx * 16, src + idx * 16);
        }
    };
    auto loadB = [&](int cg) {
        int rs = cg >> 3, ci0 = (cg & 7) * 32;
        int r = rs / 3, s = rs - 3 * (rs / 3);
        int hh = h0 + r - 1, ww = w0 + s - 1;
        bool v = pv && (unsigned)hh < (unsigned)H && (unsigned)ww < (unsigned)W;
        const uint32_t* xp = x + (size_t)(ci0 + kh * 16) * HW + (v ? (hh * W + ww) : 0);
#pragma unroll
        for (int j = 0; j < 16; j++) xw[j] = v ? xp[(size_t)j * HW] : 0u;
    };
    auto storeB = [&](int buf) {
        char* Bh = smem + buf * STAGEB + CHUNKB;
        char* Bl = Bh + BTILE;
        int off = pxl * 80 + kh * 32;
#pragma unroll
        for (int j = 0; j < 16; j += 2) {
            *(uint32_t*)(Bh + off + j * 2) = __byte_perm(xw[j], xw[j + 1], 0x5410);
            *(uint32_t*)(Bl + off + j * 2) = __byte_perm(xw[j], xw[j + 1], 0x7632);
        }
    };
    auto compute = [&](int buf) {
        uint32_t Ab = sb + buf * STAGEB;
        uint32_t Bb = Ab + CHUNKB;
#pragma unroll
        for (int ks = 0; ks < 2; ks++) {
            uint32_t aw[2][4], bh[8][2], bl[8][2];
#pragma unroll
            for (int mi = 0; mi < 2; mi++)
                ldmx4(aw[mi], Ab + aoff[mi] + ks * 32);
#pragma unroll
            for (int np = 0; np < 4; np++) {
                uint32_t r[4];
                ldmx4(r, Bb + boff[np] + ks * 32);
                bh[2 * np][0] = r[0]; bh[2 * np][1] = r[1];
                bh[2 * np + 1][0] = r[2]; bh[2 * np + 1][1] = r[3];
                ldmx4(r, Bb + BTILE + boff[np] + ks * 32);
                bl[2 * np][0] = r[0]; bl[2 * np][1] = r[1];
                bl[2 * np + 1][0] = r[2]; bl[2 * np + 1][1] = r[3];
            }
#pragma unroll
            for (int mi = 0; mi < 2; mi++)
#pragma unroll
                for (int ni = 0; ni < 8; ni++) {
                    mma_f16(acc[mi][ni], aw[mi], bh[ni]);
                    mma_f16(acc[mi][ni], aw[mi], bl[ni]);
                }
        }
    };

    // prologue
    cpaA(0, c0); CP_COMMIT();
    loadB(c0); storeB(0);
    CP_WAIT0();
    __syncthreads();

    int buf = 0;
    for (int it = 0; it < chunksPerZ; it++) {
        bool more = (it + 1) < chunksPerZ;
        if (more) { cpaA(buf ^ 1, c0 + it + 1); CP_COMMIT(); loadB(c0 + it + 1); }
        compute(buf);
        if (more) { storeB(buf ^ 1); CP_WAIT0(); }
        __syncthreads();
        buf ^= 1;
    }

    // epilogue
    float scl = (mode == 2) ? *scale_ptr : 1.f;
    size_t zoff = (size_t)blockIdx.z * (size_t)Cout * HW;
    int gid = lane >> 2, tig = lane & 3;
#pragma unroll
    for (int mi = 0; mi < 2; mi++) {
#pragma unroll
        for (int rh = 0; rh < 2; rh++) {
            int co = co0 + co_w + mi * 16 + gid + rh * 8;
            if (co >= Cout) continue;
            float bv = (mode != 0) ? bias[co] : 0.f;
            float* ob = out; int coo = co;
            if (mode == 1 && co >= split) { ob = out2; coo = co - split; }
            size_t base = (mode == 0 ? zoff : (size_t)0) + (size_t)coo * HW;
#pragma unroll
            for (int ni = 0; ni < 8; ni++) {
                int px = px0 + px_w + ni * 8 + tig * 2;
                if (px >= HW) continue;
                float v0 = acc[mi][ni][rh * 2], v1 = acc[mi][ni][rh * 2 + 1];
                if (mode == 1) { v0 += bv; v1 += bv; }
                else if (mode == 2) { v0 = expf((v0 + bv) * scl); v1 = expf((v1 + bv) * scl); }
                float2 vv = {v0, v1};
                *(float2*)(ob + base + px) = vv;
            }
        }
    }
}

// ---- split-K reduces --------------------------------------------------------
__global__ void reduce_t(const float* __restrict__ part, int S, int HW,
                         float* __restrict__ out) {
    int idx = blockIdx.x * blockDim.x + threadIdx.x;
    int CHW = 256 * HW;
    if (idx >= 3 * CHW) return;
    int t = idx / CHW, r = idx - t * CHW;
    const float* p = part + (size_t)t * S * CHW + r;
    float s = 0.f;
    for (int j = 0; j < S; j++) s += p[(size_t)j * CHW];
    out[(size_t)t * YSTRIDE + r] = s;
}

__global__ void reduce_ep(const float* __restrict__ part, int S, int Cout, int HW,
                          float* __restrict__ out, float* __restrict__ out2,
                          int mode, const float* __restrict__ bias,
                          const float* __restrict__ scale_ptr, int split) {
    int i = blockIdx.x * blockDim.x + threadIdx.x;
    int CHW = Cout * HW;
    if (i >= CHW) return;
    float s = 0.f;
    for (int j = 0; j < S; j++) s += part[(size_t)j * CHW + i];
    int co = i / HW;
    float bv = (bias != nullptr) ? bias[co] : 0.f;
    if (mode == 2) { out[i] = expf((s + bv) * (*scale_ptr)); return; }
    int p = i - co * HW;
    if (co >= split) out2[(size_t)(co - split) * HW + p] = s + bv;
    else             out [(size_t)co * HW + p]           = s + bv;
}

// ---- host -------------------------------------------------------------------
extern "C" void kernel_launch(void* const* d_in, const int* in_sizes, int n_in,
                              void* d_out, int out_size) {
    (void)in_sizes; (void)n_in; (void)out_size;
    const float* feat[5];
    for (int l = 0; l < 5; l++) feat[l] = (const float*)d_in[l];
    const float* tw[3] = {(const float*)d_in[5], (const float*)d_in[8], (const float*)d_in[11]};
    const float* tg[3] = {(const float*)d_in[6], (const float*)d_in[9], (const float*)d_in[12]};
    const float* tb[3] = {(const float*)d_in[7], (const float*)d_in[10], (const float*)d_in[13]};
    const float* pcls_w = (const float*)d_in[14];
    const float* pcls_b = (const float*)d_in[15];
    const float* preg_w = (const float*)d_in[16];
    const float* preg_b = (const float*)d_in[17];
    const float* pmsk_w = (const float*)d_in[18];
    const float* pmsk_b = (const float*)d_in[19];
    const float* pctr_w = (const float*)d_in[20];
    const float* pctr_b = (const float*)d_in[21];
    const float* sc_bbox = (const float*)d_in[22];
    const float* sc_mask = (const float*)d_in[23];
    float* outf = (float*)d_out;

    float *bufA, *bufP, *aff, *biasA;
    uint32_t* bufC;
    double* gpart;
    char* wpk;
    cudaGetSymbolAddress((void**)&bufA, g_bufA);
    cudaGetSymbolAddress((void**)&bufC, g_bufC);
    cudaGetSymbolAddress((void**)&bufP, g_bufP);
    cudaGetSymbolAddress((void**)&wpk, g_wpk);
    cudaGetSymbolAddress((void**)&aff, g_aff);
    cudaGetSymbolAddress((void**)&gpart, g_gpart);
    cudaGetSymbolAddress((void**)&biasA, g_biasA);

    cudaFuncSetAttribute(conv_mma, cudaFuncAttributeMaxDynamicSharedMemorySize, SMEM_TOTAL);

    long long tot = 12LL * 256 * KTOT;
    pack_tower<<<(unsigned)((tot + 255) / 256), 256>>>(tw[0], tw[1], tw[2], wpk);
    pack_head<<<(128 * KTOT + 255) / 256, 256>>>(pcls_w, pctr_w, 80, 1, wpk + HOFFP);
    pack_head<<<(128 * KTOT + 255) / 256, 256>>>(preg_w, nullptr, 4, 0, wpk + HOFFP + CBLKB);
    pack_head<<<(128 * KTOT + 255) / 256, 256>>>(pmsk_w, nullptr, 36, 0, wpk + HOFFP + 2 * CBLKB);
    build_biasA<<<1, 128>>>(pcls_b, pctr_b, biasA);

    static const int Hs[5]  = {160, 80, 40, 20, 10};
    static const int Wss[5] = {256, 128, 64, 32, 16};
    static const int Sl[5]  = {1, 2, 6, 12, 18};
    static const int Sgl[5] = {4, 2, 1, 1, 1};
    static const size_t PHW[5] = {0, 40960, 51200, 53760, 54400};
    const size_t TOT = 54560;
    const size_t clsBase = 0, bboxBase = 80 * TOT, ctrBase = 84 * TOT, maskBase = 85 * TOT;
    const int BIG = 1 << 30;

    for (int l = 0; l < 5; l++) {
        int H = Hs[l], W = Wss[l], HW = H * W;
        int S = Sl[l], cpz = NCH / S, Sg = Sgl[l];
        int gx = (HW + 127) / 128;
        cvt_act<<<(256 * (HW >> 2) + 255) / 256, 256>>>(feat[l], nullptr, bufC, HW, 1);
        size_t xT = 0;
        for (int i = 0; i < 4; i++) {
            const char* wc = wpk + (size_t)i * CONVPK;
            if (S == 1) {
                conv_mma<<<dim3(gx, 6, 1), 256, SMEM_TOTAL>>>(bufC, wc, bufA, nullptr,
                    H, W, 256, 2, cpz, 0, nullptr, nullptr, BIG, xT, 4 * CONVPK, YSTRIDE);
            } else {
                size_t PS = (size_t)S * 256 * HW;
                conv_mma<<<dim3(gx, 6, S), 256, SMEM_TOTAL>>>(bufC, wc, bufP, nullptr,
                    H, W, 256, 2, cpz, 0, nullptr, nullptr, BIG, xT, 4 * CONVPK, PS);
                reduce_t<<<(3 * 256 * HW + 255) / 256, 256>>>(bufP, S, HW, bufA);
            }
            gn_part<<<3 * 32 * Sg, 256>>>(bufA, HW, Sg, gpart);
            gn_fin<<<1, 768>>>(gpart, Sg, HW,
                tg[0] + i * FEAT, tg[1] + i * FEAT, tg[2] + i * FEAT,
                tb[0] + i * FEAT, tb[1] + i * FEAT, tb[2] + i * FEAT, aff);
            cvt_act<<<(3 * 256 * (HW >> 2) + 255) / 256, 256>>>(bufA, aff, bufC, HW, 3);
            xT = YSTRIDE;
        }
        for (int t = 0; t < 3; t++) {
            const uint32_t* hx = bufC + (size_t)t * YSTRIDE;
            const char* hw = wpk + HOFFP + (size_t)t * CBLKB;
            int Cout, mode, split = BIG;
            const float* bias; const float* scp = nullptr;
            float *o1, *o2 = nullptr;
            if (t == 0) {
                Cout = 81; mode = 1; split = 80; bias = biasA;
                o1 = outf + clsBase + 80 * PHW[l];
                o2 = outf + ctrBase + PHW[l];
            } else if (t == 1) {
                Cout = 4; mode = 2; bias = preg_b; scp = sc_bbox + l;
                o1 = outf + bboxBase + 4 * PHW[l];
            } else {
                Cout = 36; mode = 2; bias = pmsk_b; scp = sc_mask + l;
                o1 = outf + maskBase + 36 * PHW[l];
            }
            if (S == 1) {
                conv_mma<<<dim3(gx, 1, 1), 256, SMEM_TOTAL>>>(hx, hw, o1, o2,
                    H, W, Cout, 1, cpz, mode, bias, scp, split, 0, 0, 0);
            } else {
                conv_mma<<<dim3(gx, 1, S), 256, SMEM_TOTAL>>>(hx, hw, bufP, nullptr,
                    H, W, Cout, 1, cpz, 0, nullptr, nullptr, BIG, 0, 0, 0);
                reduce_ep<<<(Cout * HW + 255) / 256, 256>>>(bufP, S, Cout, HW,
                    o1, o2, mode, bias, scp, split);
            }
        }
    }
}